// round 13
// baseline (speedup 1.0000x reference)
#include <cuda_runtime.h>
#include <cuda_fp16.h>
#include <math.h>
#include <stdint.h>

#define Bm   2
#define Sm   2048
#define Dm   1024
#define Hm   16
#define DHm  64
#define MROWS (Bm*Sm)      // 4096
#define QKVN  (3*Dm)       // 3072

// ---------------- scratch (device globals; no allocation) ----------------
__device__ float g_cos[Sm * DHm];
__device__ float g_sin[Sm * DHm];

// fp16 buffers
__device__ __half g_xf [MROWS * Dm];      // x
__device__ __half g_wf [QKVN * Dm];       // qkv_w
__device__ __half g_pf [Dm * Dm];         // proj_w
// rope'd q/k/v, fp16, [B,H,S,Dh]  (q pre-scaled by 0.125)
__device__ __half g_qf [Bm*Hm*Sm*DHm];
__device__ __half g_kf [Bm*Hm*Sm*DHm];
__device__ __half g_vf [Bm*Hm*Sm*DHm];
// attention context, fp16 [B*S, D]
__device__ __half g_cf [MROWS * Dm];

// ---------------- helpers ----------------
__device__ __forceinline__ uint32_t smem_u32(const void* p) {
    uint32_t a;
    asm("{ .reg .u64 t; cvta.to.shared.u64 t, %1; cvt.u32.u64 %0, t; }" : "=r"(a) : "l"(p));
    return a;
}
__device__ __forceinline__ void ldsm4(uint32_t* r, uint32_t addr) {
    asm volatile("ldmatrix.sync.aligned.m8n8.x4.shared.b16 {%0,%1,%2,%3}, [%4];"
                 : "=r"(r[0]), "=r"(r[1]), "=r"(r[2]), "=r"(r[3]) : "r"(addr));
}
__device__ __forceinline__ void ldsm4t(uint32_t* r, uint32_t addr) {
    asm volatile("ldmatrix.sync.aligned.m8n8.x4.trans.shared.b16 {%0,%1,%2,%3}, [%4];"
                 : "=r"(r[0]), "=r"(r[1]), "=r"(r[2]), "=r"(r[3]) : "r"(addr));
}
__device__ __forceinline__ void mma16816h(float* c, const uint32_t* a, uint32_t b0, uint32_t b1) {
    asm volatile("mma.sync.aligned.m16n8k16.row.col.f32.f16.f16.f32 "
                 "{%0,%1,%2,%3}, {%4,%5,%6,%7}, {%8,%9}, {%0,%1,%2,%3};"
                 : "+f"(c[0]), "+f"(c[1]), "+f"(c[2]), "+f"(c[3])
                 : "r"(a[0]), "r"(a[1]), "r"(a[2]), "r"(a[3]), "r"(b0), "r"(b1));
}
__device__ __forceinline__ uint32_t packhf(float lo, float hi) {
    __half2 v = __floats2half2_rn(lo, hi);
    return *(uint32_t*)&v;
}

// ---------------- combined fp32->fp16 convert + rope table ----------------
#define N1 (MROWS * Dm / 4)
#define N2 (QKVN * Dm / 4)
#define N3 (Dm * Dm / 4)
#define NT (Sm * DHm)

__global__ void conv_all_kernel(const float* __restrict__ x,
                                const float* __restrict__ qw,
                                const float* __restrict__ pw) {
    int i = blockIdx.x * blockDim.x + threadIdx.x;
    if (i < N1 + N2 + N3) {
        const float* src;
        __half* dst;
        int off;
        if (i < N1)           { src = x;  dst = g_xf; off = i; }
        else if (i < N1 + N2) { src = qw; dst = g_wf; off = i - N1; }
        else                  { src = pw; dst = g_pf; off = i - N1 - N2; }
        float4 v = ((const float4*)src)[off];
        ((__half2*)dst)[off * 2 + 0] = __floats2half2_rn(v.x, v.y);
        ((__half2*)dst)[off * 2 + 1] = __floats2half2_rn(v.z, v.w);
    } else if (i < N1 + N2 + N3 + NT) {
        int j = i - (N1 + N2 + N3);
        int s = j >> 6, d = j & 63, fi = d & 31;
        double inv = exp2(-(double)(2 * fi) / 64.0 * 13.287712379549449);  // log2(10000)
        double ang = fmod((double)s * inv, 6.283185307179586476925287);
        float sn, cs;
        sincosf((float)ang, &sn, &cs);
        g_cos[j] = cs;
        g_sin[j] = sn;
    }
}

// ---------------- mma.sync single-pass fp16 GEMM, KC=64 double-buffered ----------------
// MODE 0: C[m,n] = sum_k A*B + bias -> fp32 out
// MODE 1: QKV epilogue -> rope + scatter fp16 to g_qf/g_kf/g_vf (q scaled 0.125)
#define KC 64
#define LDT 72
#define TILE_E (128*LDT)
#define STAGE_E (2*TILE_E)        // A, B
#define CST 130                   // fp32 C-tile smem stride (floats)

template<int MODE>
__global__ __launch_bounds__(256, 2)
void mma_gemm_fp16_kernel(const __half* __restrict__ A, const __half* __restrict__ B,
                          const float* __restrict__ bias, float* __restrict__ C,
                          int M, int N, int K)
{
    extern __shared__ __half sm[];
    int tid = threadIdx.x;
    int lane = tid & 31, wid = tid >> 5;
    int wm = wid & 1, wn = wid >> 1;
    int m0 = blockIdx.y * 128, n0 = blockIdx.x * 128;
    int NC = K / KC;
    uint32_t sb = smem_u32(sm);

    float acc[4][4][4];
#pragma unroll
    for (int mt = 0; mt < 4; mt++)
#pragma unroll
        for (int nt = 0; nt < 4; nt++)
#pragma unroll
            for (int r = 0; r < 4; r++) acc[mt][nt][r] = 0.0f;

    auto issue = [&](int kc, int stg) {
#pragma unroll
        for (int i = 0; i < 8; i++) {
            int c = tid + (i << 8);
            int tile = c >> 10;
            int r = (c >> 3) & 127;
            int q = c & 7;
            uint32_t sa = sb + (uint32_t)(stg * STAGE_E + tile * TILE_E + r * LDT + q * 8) * 2;
            const __half* g = (tile == 0) ? (A + (size_t)(m0 + r) * K)
                                          : (B + (size_t)(n0 + r) * K);
            g += kc * KC + q * 8;
            asm volatile("cp.async.cg.shared.global [%0], [%1], 16;" :: "r"(sa), "l"(g));
        }
        asm volatile("cp.async.commit_group;" ::: "memory");
    };

    issue(0, 0);

    for (int kc = 0; kc < NC; kc++) {
        int stg = kc & 1;
        if (kc + 1 < NC) issue(kc + 1, (kc + 1) & 1);
        if (kc + 1 < NC)
            asm volatile("cp.async.wait_group 1;" ::: "memory");
        else
            asm volatile("cp.async.wait_group 0;" ::: "memory");
        __syncthreads();

        uint32_t abase = sb + (uint32_t)(stg * STAGE_E) * 2
                       + (uint32_t)((wm * 64 + (lane & 15)) * LDT + (lane >> 4) * 8) * 2;
        uint32_t bbase = sb + (uint32_t)(stg * STAGE_E + TILE_E) * 2
                       + (uint32_t)((wn * 32 + (lane & 15)) * LDT + (lane >> 4) * 8) * 2;

#pragma unroll
        for (int kt = 0; kt < 4; kt++) {
            uint32_t kb = (uint32_t)(kt * 16) * 2;
            uint32_t ah[4][4], bh[2][4];
#pragma unroll
            for (int mt = 0; mt < 4; mt++)
                ldsm4(ah[mt], abase + (uint32_t)(mt * 16 * LDT) * 2 + kb);
#pragma unroll
            for (int nt2 = 0; nt2 < 2; nt2++)
                ldsm4(bh[nt2], bbase + (uint32_t)(nt2 * 16 * LDT) * 2 + kb);
#pragma unroll
            for (int mt = 0; mt < 4; mt++)
#pragma unroll
                for (int nt = 0; nt < 4; nt++) {
                    int n2 = nt >> 1, hf = nt & 1;
                    mma16816h(acc[mt][nt], ah[mt], bh[n2][hf], bh[n2][hf + 2]);
                }
        }
        __syncthreads();
    }

    if (MODE == 0) {
        // ---- fp32 direct epilogue (proj) ----
#pragma unroll
        for (int mt = 0; mt < 4; mt++) {
            int row = m0 + wm * 64 + mt * 16 + (lane >> 2);
#pragma unroll
            for (int nt = 0; nt < 4; nt++) {
                int col = n0 + wn * 32 + nt * 8 + (lane & 3) * 2;
                float b0 = bias[col], b1 = bias[col + 1];
                *(float2*)&C[(size_t)row * N + col] =
                    make_float2(acc[mt][nt][0] + b0, acc[mt][nt][1] + b1);
                *(float2*)&C[(size_t)(row + 8) * N + col] =
                    make_float2(acc[mt][nt][2] + b0, acc[mt][nt][3] + b1);
            }
        }
    } else {
        // ---- QKV epilogue: stage C tile in smem, rope + scatter fp16 ----
        float* S = (float*)sm;
#pragma unroll
        for (int mt = 0; mt < 4; mt++) {
            int row = wm * 64 + mt * 16 + (lane >> 2);
#pragma unroll
            for (int nt = 0; nt < 4; nt++) {
                int col = wn * 32 + nt * 8 + (lane & 3) * 2;
                float b0 = bias[n0 + col], b1 = bias[n0 + col + 1];
                S[row * CST + col]           = acc[mt][nt][0] + b0;
                S[row * CST + col + 1]       = acc[mt][nt][1] + b1;
                S[(row + 8) * CST + col]     = acc[mt][nt][2] + b0;
                S[(row + 8) * CST + col + 1] = acc[mt][nt][3] + b1;
            }
        }
        __syncthreads();

        int r  = tid >> 1;          // tile row 0..127
        int hh = tid & 1;           // head-half of tile (64 cols each)
        int gr = m0 + r;
        int b  = gr >> 11;
        int s  = gr & 2047;
        int C0 = n0 + hh * 64;
        int region = C0 >> 10;             // 0=q 1=k 2=v
        int h = (C0 & 1023) >> 6;
        __half* dst = (region == 0) ? g_qf : (region == 1) ? g_kf : g_vf;
        size_t obase = ((size_t)(b * Hm + h) * Sm + s) * DHm;
        const float* Srow = S + r * CST + hh * 64;

        if (region == 2) {
#pragma unroll
            for (int d = 0; d < 64; d += 2)
                *(uint32_t*)&dst[obase + d] = packhf(Srow[d], Srow[d + 1]);
        } else {
            float qs = (region == 0) ? 0.125f : 1.0f;
            const float* cosr = g_cos + (s << 6);
            const float* sinr = g_sin + (s << 6);
#pragma unroll 8
            for (int d = 0; d < 64; d += 2) {
                float sgn = (d < 32) ? -1.0f : 1.0f;
                float v0 = fmaf(Srow[d],     cosr[d],     sgn * Srow[d ^ 32]       * sinr[d])     * qs;
                float v1 = fmaf(Srow[d + 1], cosr[d + 1], sgn * Srow[(d + 1) ^ 32] * sinr[d + 1]) * qs;
                *(uint32_t*)&dst[obase + d] = packhf(v0, v1);
            }
        }
    }
}

// ---------------- flash attention on mma.sync fp16 (causal; q pre-scaled) ----------------
#define LDK 72
#define QSZ (128*LDK)
#define KSZ (64*LDK)
#define STG (2*KSZ)              // kf, vf

__global__ __launch_bounds__(256, 2)
void attn_mma_kernel() {
    extern __shared__ __half asm_[];
    uint32_t sb = smem_u32(asm_);
    int tid = threadIdx.x;
    int lane = tid & 31, w = tid >> 5;
    int bh = blockIdx.y;
    int bidx = bh >> 4, hidx = bh & 15;
    int i0 = blockIdx.x * 128;
    int wr0 = w * 16;
    int ntiles = 2 * blockIdx.x + 2;

    auto issue_kv = [&](int jt, int stg) {
        int j0 = jt * 64;
#pragma unroll
        for (int i = 0; i < 4; i++) {
            int c = tid + (i << 8);
            int tile = c >> 9;               // 0=kf 1=vf
            int r = (c >> 3) & 63;
            int q = c & 7;
            uint32_t sa = sb + (uint32_t)(QSZ + stg * STG + tile * KSZ + r * LDK + q * 8) * 2;
            const __half* g = (tile == 0) ? g_kf : g_vf;
            g += ((size_t)bh * Sm + j0 + r) * DHm + q * 8;
            asm volatile("cp.async.cg.shared.global [%0], [%1], 16;" :: "r"(sa), "l"(g));
        }
        asm volatile("cp.async.commit_group;" ::: "memory");
    };

#pragma unroll
    for (int i = 0; i < 4; i++) {
        int c = tid + (i << 8);
        int r = c >> 3, q = c & 7;
        uint32_t sa = sb + (uint32_t)(r * LDK + q * 8) * 2;
        const __half* g = g_qf + ((size_t)bh * Sm + i0 + r) * DHm + q * 8;
        asm volatile("cp.async.cg.shared.global [%0], [%1], 16;" :: "r"(sa), "l"(g));
    }
    issue_kv(0, 0);
    asm volatile("cp.async.commit_group;" ::: "memory");

    float O[8][4];
#pragma unroll
    for (int nt = 0; nt < 8; nt++)
#pragma unroll
        for (int r = 0; r < 4; r++) O[nt][r] = 0.0f;
    float m_lo = -1e30f, m_hi = -1e30f, l_lo = 0.0f, l_hi = 0.0f;

    int gi_lo = i0 + wr0 + (lane >> 2);
    int gi_hi = gi_lo + 8;
    int colb = (lane & 3) << 1;

    for (int jt = 0; jt < ntiles; jt++) {
        int stg = jt & 1;
        int j0 = jt * 64;
        if (jt + 1 < ntiles) issue_kv(jt + 1, (jt + 1) & 1);
        if (jt + 1 < ntiles)
            asm volatile("cp.async.wait_group 1;" ::: "memory");
        else
            asm volatile("cp.async.wait_group 0;" ::: "memory");
        __syncthreads();

        bool skip = (j0 > i0 + wr0 + 15);
        if (!skip) {
            uint32_t SB2 = QSZ + stg * STG;
            float c[8][4];
#pragma unroll
            for (int nt = 0; nt < 8; nt++)
#pragma unroll
                for (int r = 0; r < 4; r++) c[nt][r] = 0.0f;

            uint32_t qoffe = (uint32_t)((wr0 + (lane & 15)) * LDK + (lane >> 4) * 8);
            uint32_t koffe = (uint32_t)(((lane & 15)) * LDK + (lane >> 4) * 8);
#pragma unroll
            for (int kc = 0; kc < 4; kc++) {
                uint32_t qa = sb + (qoffe + kc * 16) * 2;
                uint32_t qah[4];
                ldsm4(qah, qa);
#pragma unroll
                for (int np = 0; np < 4; np++) {
                    uint32_t ka = sb + (SB2 + np * 16 * LDK + koffe + kc * 16) * 2;
                    uint32_t kbh[4];
                    ldsm4(kbh, ka);
                    mma16816h(c[2*np],   qah, kbh[0], kbh[2]);
                    mma16816h(c[2*np+1], qah, kbh[1], kbh[3]);
                }
            }

            bool needmask = (j0 + 63) > (i0 + wr0);
            float mxlo = -1e30f, mxhi = -1e30f;
#pragma unroll
            for (int nt = 0; nt < 8; nt++) {
                float s0 = c[nt][0], s1 = c[nt][1];
                float s2 = c[nt][2], s3 = c[nt][3];
                if (needmask) {
                    int j = j0 + nt * 8 + colb;
                    if (j     > gi_lo) s0 = -1e30f;
                    if (j + 1 > gi_lo) s1 = -1e30f;
                    if (j     > gi_hi) s2 = -1e30f;
                    if (j + 1 > gi_hi) s3 = -1e30f;
                }
                c[nt][0] = s0; c[nt][1] = s1; c[nt][2] = s2; c[nt][3] = s3;
                mxlo = fmaxf(mxlo, fmaxf(s0, s1));
                mxhi = fmaxf(mxhi, fmaxf(s2, s3));
            }
            mxlo = fmaxf(mxlo, __shfl_xor_sync(0xffffffffu, mxlo, 1));
            mxlo = fmaxf(mxlo, __shfl_xor_sync(0xffffffffu, mxlo, 2));
            mxhi = fmaxf(mxhi, __shfl_xor_sync(0xffffffffu, mxhi, 1));
            mxhi = fmaxf(mxhi, __shfl_xor_sync(0xffffffffu, mxhi, 2));
            float mnlo = fmaxf(m_lo, mxlo), mnhi = fmaxf(m_hi, mxhi);
            float alo = __expf(m_lo - mnlo), ahi = __expf(m_hi - mnhi);
            float slo = 0.0f, shi = 0.0f;
#pragma unroll
            for (int nt = 0; nt < 8; nt++) {
                float p0 = __expf(c[nt][0] - mnlo);
                float p1 = __expf(c[nt][1] - mnlo);
                float p2 = __expf(c[nt][2] - mnhi);
                float p3 = __expf(c[nt][3] - mnhi);
                c[nt][0] = p0; c[nt][1] = p1; c[nt][2] = p2; c[nt][3] = p3;
                slo += p0 + p1; shi += p2 + p3;
            }
            slo += __shfl_xor_sync(0xffffffffu, slo, 1);
            slo += __shfl_xor_sync(0xffffffffu, slo, 2);
            shi += __shfl_xor_sync(0xffffffffu, shi, 1);
            shi += __shfl_xor_sync(0xffffffffu, shi, 2);
            l_lo = l_lo * alo + slo; m_lo = mnlo;
            l_hi = l_hi * ahi + shi; m_hi = mnhi;
#pragma unroll
            for (int nt = 0; nt < 8; nt++) {
                O[nt][0] *= alo; O[nt][1] *= alo;
                O[nt][2] *= ahi; O[nt][3] *= ahi;
            }

            uint32_t pah[4][4];
#pragma unroll
            for (int kc = 0; kc < 4; kc++) {
#pragma unroll
                for (int half = 0; half < 2; half++) {
                    int nt = 2 * kc + half;
                    pah[kc][half * 2 + 0] = packhf(c[nt][0], c[nt][1]);
                    pah[kc][half * 2 + 1] = packhf(c[nt][2], c[nt][3]);
                }
            }

#pragma unroll
            for (int kc = 0; kc < 4; kc++) {
                uint32_t voffe = (uint32_t)(SB2 + KSZ + (kc * 16 + (lane & 15)) * LDK
                                            + (lane >> 4) * 8);
#pragma unroll
                for (int np = 0; np < 4; np++) {
                    uint32_t va = sb + (voffe + np * 16) * 2;
                    uint32_t vbh[4];
                    ldsm4t(vbh, va);
                    mma16816h(O[2*np],   pah[kc], vbh[0], vbh[1]);
                    mma16816h(O[2*np+1], pah[kc], vbh[2], vbh[3]);
                }
            }
        }
        __syncthreads();
    }

    float ivlo = 1.0f / l_lo, ivhi = 1.0f / l_hi;
    size_t rlo = (size_t)(bidx * Sm + gi_lo) * Dm;
    size_t rhi = (size_t)(bidx * Sm + gi_hi) * Dm;
#pragma unroll
    for (int nt = 0; nt < 8; nt++) {
        int col = hidx * DHm + nt * 8 + colb;
        *(uint32_t*)&g_cf[rlo + col] = packhf(O[nt][0] * ivlo, O[nt][1] * ivlo);
        *(uint32_t*)&g_cf[rhi + col] = packhf(O[nt][2] * ivhi, O[nt][3] * ivhi);
    }
}

// ---------------- launch ----------------
extern "C" void kernel_launch(void* const* d_in, const int* in_sizes, int n_in,
                              void* d_out, int out_size)
{
    const float* x      = (const float*)d_in[0];
    const float* qkv_w  = (const float*)d_in[1];
    const float* qkv_b  = (const float*)d_in[2];
    const float* proj_w = (const float*)d_in[3];
    const float* proj_b = (const float*)d_in[4];
    float* out = (float*)d_out;

    __half *p_xf, *p_wf, *p_pf, *p_cf;
    cudaGetSymbolAddress((void**)&p_xf, g_xf);
    cudaGetSymbolAddress((void**)&p_wf, g_wf);
    cudaGetSymbolAddress((void**)&p_pf, g_pf);
    cudaGetSymbolAddress((void**)&p_cf, g_cf);

    int smem_gemm = 2 * STAGE_E * sizeof(__half);          // 73728 (>= 128*130*4=66560)
    cudaFuncSetAttribute(mma_gemm_fp16_kernel<0>,
                         cudaFuncAttributeMaxDynamicSharedMemorySize, smem_gemm);
    cudaFuncSetAttribute(mma_gemm_fp16_kernel<1>,
                         cudaFuncAttributeMaxDynamicSharedMemorySize, smem_gemm);
    int smem_attn = (QSZ + 2 * STG) * sizeof(__half);      // 55296
    cudaFuncSetAttribute(attn_mma_kernel, cudaFuncAttributeMaxDynamicSharedMemorySize, smem_attn);

    // 1) convert inputs to fp16 + rope table (one kernel)
    conv_all_kernel<<<(N1 + N2 + N3 + NT + 255) / 256, 256>>>(x, qkv_w, proj_w);

    // 2) QKV GEMM with fused rope/scatter epilogue -> g_qf/g_kf/g_vf
    mma_gemm_fp16_kernel<1><<<dim3(QKVN / 128, MROWS / 128), 256, smem_gemm>>>(
        p_xf, p_wf, qkv_b, nullptr, MROWS, QKVN, Dm);

    // 3) flash attention (fp16 mma) -> g_cf
    attn_mma_kernel<<<dim3(Sm / 128, Bm * Hm), 256, smem_attn>>>();

    // 4) proj GEMM (fp32 out)
    mma_gemm_fp16_kernel<0><<<dim3(Dm / 128, MROWS / 128), 256, smem_gemm>>>(
        p_cf, p_pf, proj_b, out, MROWS, Dm, Dm);
}